// round 11
// baseline (speedup 1.0000x reference)
#include <cuda_runtime.h>
#include <cuda_fp16.h>
#include <math.h>

#define Nn 10000
#define Ee 320000
#define ET (Ee + Nn)   // edges + self loops
#define DH 256
#define DOUT 64

// ---------------- device scratch (no cudaMalloc allowed) ----------------
__device__ __half g_xl[Nn * DH];
__device__ __half g_xr[Nn * DH];
__device__ __half g_h[Nn * DH];
__device__ int    g_csr_src[ET];
__device__ int    g_cnt[Nn];
__device__ int    g_row_ptr[Nn + 1];
__device__ int    g_row_off[Nn];
__device__ int    g_flag_i64[1];

// ---------------- combined zero + dtype detect ----------------
__global__ void k_zero_detect(const int* ei32) {
    int i = blockIdx.x * blockDim.x + threadIdx.x;
    if (i < Nn) g_cnt[i] = 0;
    if (i == 0) {
        int all0 = 1;
        for (int j = 0; j < 64; ++j) {
            if (ei32[2 * j + 1] != 0) { all0 = 0; break; }
        }
        g_flag_i64[0] = all0;
    }
}

__device__ __forceinline__ int edge_val(const void* ei, long long idx, int is64) {
    if (is64) return (int)((const long long*)ei)[idx];
    return ((const int*)ei)[idx];
}

__global__ void k_hist(const void* ei) {
    int e = blockIdx.x * blockDim.x + threadIdx.x;
    if (e >= ET) return;
    int is64 = g_flag_i64[0];
    int dst = (e >= Ee) ? (e - Ee) : edge_val(ei, (long long)Ee + e, is64);
    atomicAdd(&g_cnt[dst], 1);
}

// hierarchical shuffle scan: 1024 threads x 10 elems
__global__ __launch_bounds__(1024) void k_scan() {
    __shared__ int wsum[32];
    int tid = threadIdx.x;
    int lane = tid & 31, w = tid >> 5;
    int base = tid * 10;
    int c[10];
    int s = 0;
#pragma unroll
    for (int i = 0; i < 10; ++i) {
        int idx = base + i;
        c[i] = (idx < Nn) ? g_cnt[idx] : 0;
        s += c[i];
    }
    int incl = s;
#pragma unroll
    for (int o = 1; o < 32; o <<= 1) {
        int v = __shfl_up_sync(0xffffffffu, incl, o);
        if (lane >= o) incl += v;
    }
    if (lane == 31) wsum[w] = incl;
    __syncthreads();
    if (w == 0) {
        int wi = wsum[lane];
#pragma unroll
        for (int o = 1; o < 32; o <<= 1) {
            int t = __shfl_up_sync(0xffffffffu, wi, o);
            if (lane >= o) wi += t;
        }
        wsum[lane] = wi;
    }
    __syncthreads();
    int excl = incl - s + (w > 0 ? wsum[w - 1] : 0);
    int run = excl;
#pragma unroll
    for (int i = 0; i < 10; ++i) {
        int idx = base + i;
        if (idx < Nn) {
            g_row_ptr[idx] = run;
            g_row_off[idx] = run;
            run += c[i];
        }
    }
    if (tid == 0) g_row_ptr[Nn] = ET;
}

__global__ void k_scatter(const void* ei) {
    int e = blockIdx.x * blockDim.x + threadIdx.x;
    if (e >= ET) return;
    int is64 = g_flag_i64[0];
    int src, dst;
    if (e >= Ee) {
        src = dst = e - Ee;
    } else {
        src = edge_val(ei, (long long)e, is64);
        dst = edge_val(ei, (long long)Ee + e, is64);
    }
    int pos = atomicAdd(&g_row_off[dst], 1);
    g_csr_src[pos] = src;
}

// ---------------- TF32 tensor-core GEMM ----------------
__device__ __forceinline__ unsigned f2tf32(float v) {
    unsigned o;
    asm volatile("cvt.rna.tf32.f32 %0, %1;" : "=r"(o) : "f"(v));
    return o;
}

template<int BN, int WARPS_M, int MT, typename AT, typename OT>
__device__ __forceinline__ void gemm_body(
    const AT* __restrict__ A, const float* __restrict__ B,
    const float* __restrict__ bias, OT* __restrict__ C,
    int M, int Nc, int K, int row0, int col0)
{
    constexpr int BM = 128;
    constexpr int BK = 32;
    constexpr int NT = 4;
    constexpr int ASTR = 36;
    constexpr int BSTR = BN + 8;

    __shared__ unsigned As[BM][ASTR];
    __shared__ unsigned Bs[BK][BSTR];

    int tid = threadIdx.x;
    int lane = tid & 31;
    int wid = tid >> 5;
    int gid = lane >> 2;
    int tin = lane & 3;

    int wm = wid % WARPS_M;
    int wn = wid / WARPS_M;
    int mbase = wm * (MT * 16);
    int nbase = wn * 32;

    float c[MT][NT][4];
#pragma unroll
    for (int i = 0; i < MT; ++i)
#pragma unroll
        for (int j = 0; j < NT; ++j)
#pragma unroll
            for (int q = 0; q < 4; ++q) c[i][j][q] = 0.f;

    constexpr int BF4 = (BK * BN) / 4 / 256;
    constexpr int BROWF4 = BN / 4;

    for (int k0 = 0; k0 < K; k0 += BK) {
        // ---- load A tile ----
        if constexpr (sizeof(AT) == 2) {
#pragma unroll
            for (int i = 0; i < 2; ++i) {
                int idx = tid + i * 256;
                int r = idx >> 2;
                int c8 = (idx & 3) * 8;
                uint4 hv = make_uint4(0u, 0u, 0u, 0u);
                if (row0 + r < M)
                    hv = *(const uint4*)((const __half*)A + (size_t)(row0 + r) * K + k0 + c8);
                const unsigned* hu = (const unsigned*)&hv;
#pragma unroll
                for (int q = 0; q < 4; ++q) {
                    float2 p = __half22float2(*(const __half2*)&hu[q]);
                    As[r][c8 + 2 * q]     = f2tf32(p.x);
                    As[r][c8 + 2 * q + 1] = f2tf32(p.y);
                }
            }
        } else {
#pragma unroll
            for (int i = 0; i < 4; ++i) {
                int idx = tid + i * 256;
                int r = idx >> 3;
                int c4 = (idx & 7) * 4;
                float4 v = make_float4(0.f, 0.f, 0.f, 0.f);
                if (row0 + r < M)
                    v = *(const float4*)((const float*)A + (size_t)(row0 + r) * K + k0 + c4);
                uint4 t;
                t.x = f2tf32(v.x); t.y = f2tf32(v.y);
                t.z = f2tf32(v.z); t.w = f2tf32(v.w);
                *(uint4*)&As[r][c4] = t;
            }
        }
        // ---- load B tile ----
#pragma unroll
        for (int i = 0; i < BF4; ++i) {
            int idx = tid + i * 256;
            int r = idx / BROWF4;
            int c4 = (idx % BROWF4) * 4;
            float4 v = *(const float4*)(B + (size_t)(k0 + r) * Nc + col0 + c4);
            uint4 t;
            t.x = f2tf32(v.x); t.y = f2tf32(v.y);
            t.z = f2tf32(v.z); t.w = f2tf32(v.w);
            *(uint4*)&Bs[r][c4] = t;
        }
        __syncthreads();

#pragma unroll
        for (int kk = 0; kk < BK; kk += 8) {
            unsigned a[MT][4];
#pragma unroll
            for (int mt = 0; mt < MT; ++mt) {
                int r = mbase + mt * 16 + gid;
                a[mt][0] = As[r][kk + tin];
                a[mt][1] = As[r + 8][kk + tin];
                a[mt][2] = As[r][kk + tin + 4];
                a[mt][3] = As[r + 8][kk + tin + 4];
            }
            unsigned b[NT][2];
#pragma unroll
            for (int nt = 0; nt < NT; ++nt) {
                int n = nbase + nt * 8 + gid;
                b[nt][0] = Bs[kk + tin][n];
                b[nt][1] = Bs[kk + tin + 4][n];
            }
#pragma unroll
            for (int mt = 0; mt < MT; ++mt)
#pragma unroll
                for (int nt = 0; nt < NT; ++nt) {
                    asm volatile(
                        "mma.sync.aligned.m16n8k8.row.col.f32.tf32.tf32.f32 "
                        "{%0,%1,%2,%3}, {%4,%5,%6,%7}, {%8,%9}, {%0,%1,%2,%3};\n"
                        : "+f"(c[mt][nt][0]), "+f"(c[mt][nt][1]),
                          "+f"(c[mt][nt][2]), "+f"(c[mt][nt][3])
                        : "r"(a[mt][0]), "r"(a[mt][1]), "r"(a[mt][2]), "r"(a[mt][3]),
                          "r"(b[nt][0]), "r"(b[nt][1]));
                }
        }
        __syncthreads();
    }

#pragma unroll
    for (int mt = 0; mt < MT; ++mt) {
        int r0 = row0 + mbase + mt * 16 + gid;
        int r1 = r0 + 8;
#pragma unroll
        for (int nt = 0; nt < NT; ++nt) {
            int col = col0 + nbase + nt * 8 + tin * 2;
            float b0 = bias[col], b1 = bias[col + 1];
            if (r0 < M) {
                float v0 = c[mt][nt][0] + b0, v1 = c[mt][nt][1] + b1;
                if constexpr (sizeof(OT) == 2)
                    *(__half2*)((__half*)C + (size_t)r0 * Nc + col) = __floats2half2_rn(v0, v1);
                else
                    *(float2*)((float*)C + (size_t)r0 * Nc + col) = make_float2(v0, v1);
            }
            if (r1 < M) {
                float v0 = c[mt][nt][2] + b0, v1 = c[mt][nt][3] + b1;
                if constexpr (sizeof(OT) == 2)
                    *(__half2*)((__half*)C + (size_t)r1 * Nc + col) = __floats2half2_rn(v0, v1);
                else
                    *(float2*)((float*)C + (size_t)r1 * Nc + col) = make_float2(v0, v1);
            }
        }
    }
}

// dual GEMMs: layer1 (A=float), layer2 (A=half)
__global__ __launch_bounds__(256) void k_gemm_dual_f32(
    const float* __restrict__ A,
    const float* __restrict__ Bl, const float* __restrict__ biasl, __half* __restrict__ Cl,
    const float* __restrict__ Br, const float* __restrict__ biasr, __half* __restrict__ Cr,
    int M, int Nc, int K)
{
    int sel = blockIdx.x >> 1;
    int bx = blockIdx.x & 1;
    gemm_body<128, 2, 4, float, __half>(A, sel ? Br : Bl, sel ? biasr : biasl,
                                        sel ? Cr : Cl, M, Nc, K,
                                        blockIdx.y * 128, bx * 128);
}

__global__ __launch_bounds__(256) void k_gemm_dual_f16(
    const __half* __restrict__ A,
    const float* __restrict__ Bl, const float* __restrict__ biasl, __half* __restrict__ Cl,
    const float* __restrict__ Br, const float* __restrict__ biasr, __half* __restrict__ Cr,
    int M, int Nc, int K)
{
    int sel = blockIdx.x >> 1;
    int bx = blockIdx.x & 1;
    gemm_body<128, 2, 4, __half, __half>(A, sel ? Br : Bl, sel ? biasr : biasl,
                                         sel ? Cr : Cl, M, Nc, K,
                                         blockIdx.y * 128, bx * 128);
}

// ---------------- head GEMM (A=half) fused with log_softmax ----------------
__global__ __launch_bounds__(256) void k_head_fused(
    const __half* __restrict__ A, const float* __restrict__ B,
    const float* __restrict__ bias, float* __restrict__ out, int M, int K)
{
    constexpr int BM = 128, BK = 32, BN = 64;
    constexpr int WARPS_M = 4, MT = 2, NT = 4;
    constexpr int ASTR = 36, BSTR = BN + 8;
    constexpr int LSTR = 66;

    __shared__ unsigned As[BM][ASTR];
    __shared__ unsigned Bs[BK][BSTR];
    __shared__ float s_logits[BM * LSTR];

    int tid = threadIdx.x;
    int lane = tid & 31;
    int wid = tid >> 5;
    int gid = lane >> 2;
    int tin = lane & 3;

    int wm = wid % WARPS_M;
    int wn = wid / WARPS_M;
    int mbase = wm * (MT * 16);
    int nbase = wn * 32;
    int row0 = blockIdx.x * BM;

    float c[MT][NT][4];
#pragma unroll
    for (int i = 0; i < MT; ++i)
#pragma unroll
        for (int j = 0; j < NT; ++j)
#pragma unroll
            for (int q = 0; q < 4; ++q) c[i][j][q] = 0.f;

    constexpr int BF4 = (BK * BN) / 4 / 256;
    constexpr int BROWF4 = BN / 4;

    for (int k0 = 0; k0 < K; k0 += BK) {
#pragma unroll
        for (int i = 0; i < 2; ++i) {
            int idx = tid + i * 256;
            int r = idx >> 2;
            int c8 = (idx & 3) * 8;
            uint4 hv = make_uint4(0u, 0u, 0u, 0u);
            if (row0 + r < M)
                hv = *(const uint4*)(A + (size_t)(row0 + r) * K + k0 + c8);
            const unsigned* hu = (const unsigned*)&hv;
#pragma unroll
            for (int q = 0; q < 4; ++q) {
                float2 p = __half22float2(*(const __half2*)&hu[q]);
                As[r][c8 + 2 * q]     = f2tf32(p.x);
                As[r][c8 + 2 * q + 1] = f2tf32(p.y);
            }
        }
#pragma unroll
        for (int i = 0; i < BF4; ++i) {
            int idx = tid + i * 256;
            int r = idx / BROWF4;
            int c4 = (idx % BROWF4) * 4;
            float4 v = *(const float4*)(B + (size_t)(k0 + r) * BN + c4);
            uint4 t;
            t.x = f2tf32(v.x); t.y = f2tf32(v.y);
            t.z = f2tf32(v.z); t.w = f2tf32(v.w);
            *(uint4*)&Bs[r][c4] = t;
        }
        __syncthreads();

#pragma unroll
        for (int kk = 0; kk < BK; kk += 8) {
            unsigned a[MT][4];
#pragma unroll
            for (int mt = 0; mt < MT; ++mt) {
                int r = mbase + mt * 16 + gid;
                a[mt][0] = As[r][kk + tin];
                a[mt][1] = As[r + 8][kk + tin];
                a[mt][2] = As[r][kk + tin + 4];
                a[mt][3] = As[r + 8][kk + tin + 4];
            }
            unsigned b[NT][2];
#pragma unroll
            for (int nt = 0; nt < NT; ++nt) {
                int n = nbase + nt * 8 + gid;
                b[nt][0] = Bs[kk + tin][n];
                b[nt][1] = Bs[kk + tin + 4][n];
            }
#pragma unroll
            for (int mt = 0; mt < MT; ++mt)
#pragma unroll
                for (int nt = 0; nt < NT; ++nt) {
                    asm volatile(
                        "mma.sync.aligned.m16n8k8.row.col.f32.tf32.tf32.f32 "
                        "{%0,%1,%2,%3}, {%4,%5,%6,%7}, {%8,%9}, {%0,%1,%2,%3};\n"
                        : "+f"(c[mt][nt][0]), "+f"(c[mt][nt][1]),
                          "+f"(c[mt][nt][2]), "+f"(c[mt][nt][3])
                        : "r"(a[mt][0]), "r"(a[mt][1]), "r"(a[mt][2]), "r"(a[mt][3]),
                          "r"(b[nt][0]), "r"(b[nt][1]));
                }
        }
        __syncthreads();
    }

#pragma unroll
    for (int mt = 0; mt < MT; ++mt) {
        int r0 = mbase + mt * 16 + gid;
        int r1 = r0 + 8;
#pragma unroll
        for (int nt = 0; nt < NT; ++nt) {
            int col = nbase + nt * 8 + tin * 2;
            float b0 = bias[col], b1 = bias[col + 1];
            *(float2*)&s_logits[r0 * LSTR + col] =
                make_float2(c[mt][nt][0] + b0, c[mt][nt][1] + b1);
            *(float2*)&s_logits[r1 * LSTR + col] =
                make_float2(c[mt][nt][2] + b0, c[mt][nt][3] + b1);
        }
    }
    __syncthreads();

    for (int r = wid * 16; r < wid * 16 + 16; ++r) {
        int node = row0 + r;
        if (node >= M) break;
        float v0 = s_logits[r * LSTR + lane];
        float v1 = s_logits[r * LSTR + 32 + lane];
        float m = fmaxf(v0, v1);
#pragma unroll
        for (int o = 16; o > 0; o >>= 1)
            m = fmaxf(m, __shfl_xor_sync(0xffffffffu, m, o));
        float s = expf(v0 - m) + expf(v1 - m);
#pragma unroll
        for (int o = 16; o > 0; o >>= 1)
            s += __shfl_xor_sync(0xffffffffu, s, o);
        float lse = m + logf(s);
        out[(size_t)node * DOUT + lane]      = v0 - lse;
        out[(size_t)node * DOUT + 32 + lane] = v1 - lse;
    }
}

// ---------------- GATv2 layer: warp-per-node, chunked gather ----------------
__device__ __forceinline__ float warp_sum(float v) {
#pragma unroll
    for (int o = 16; o > 0; o >>= 1) v += __shfl_xor_sync(0xffffffffu, v, o);
    return v;
}

__device__ __forceinline__ float lrelu(float v) {
    return (v > 0.f) ? v : 0.2f * v;
}

__device__ __forceinline__ float score8(uint4 hv, const float* xrv, const float* atv,
                                        float* vout) {
    const unsigned* hu = (const unsigned*)&hv;
    float p = 0.f;
#pragma unroll
    for (int q = 0; q < 4; ++q) {
        float2 t = __half22float2(*(const __half2*)&hu[q]);
        vout[2 * q] = t.x; vout[2 * q + 1] = t.y;
        p = fmaf(atv[2 * q],     lrelu(t.x + xrv[2 * q]),     p);
        p = fmaf(atv[2 * q + 1], lrelu(t.y + xrv[2 * q + 1]), p);
    }
    return p;
}

__global__ __launch_bounds__(256) void k_gat_layer(
    const __half* __restrict__ xl, const __half* __restrict__ xr,
    const float* __restrict__ att, const float* __restrict__ bias,
    __half* __restrict__ out)
{
    int lane = threadIdx.x & 31;
    int w = threadIdx.x >> 5;
    int node = blockIdx.x * 8 + w;
    if (node >= Nn) return;

    // lane owns 8 contiguous dims: d = lane*8 + q
    float xrv[8], atv[8];
    {
        uint4 hx = *(const uint4*)(xr + (size_t)node * DH + lane * 8);
        const unsigned* hu = (const unsigned*)&hx;
#pragma unroll
        for (int q = 0; q < 4; ++q) {
            float2 p = __half22float2(*(const __half2*)&hu[q]);
            xrv[2 * q] = p.x; xrv[2 * q + 1] = p.y;
        }
        float4 a0 = ((const float4*)att)[lane * 2];
        float4 a1 = ((const float4*)att)[lane * 2 + 1];
        atv[0] = a0.x; atv[1] = a0.y; atv[2] = a0.z; atv[3] = a0.w;
        atv[4] = a1.x; atv[5] = a1.y; atv[6] = a1.z; atv[7] = a1.w;
    }

    int beg = g_row_ptr[node];
    int end = g_row_ptr[node + 1];

    float m_w = -INFINITY, s_w = 0.f;
    float acc[8] = {0.f, 0.f, 0.f, 0.f, 0.f, 0.f, 0.f, 0.f};

    int e = beg;
    // chunk of 4: 4 independent gathers in flight
    for (; e + 4 <= end; e += 4) {
        int s0 = g_csr_src[e];
        int s1 = g_csr_src[e + 1];
        int s2 = g_csr_src[e + 2];
        int s3 = g_csr_src[e + 3];
        uint4 h0 = *(const uint4*)(xl + (size_t)s0 * DH + lane * 8);
        uint4 h1 = *(const uint4*)(xl + (size_t)s1 * DH + lane * 8);
        uint4 h2 = *(const uint4*)(xl + (size_t)s2 * DH + lane * 8);
        uint4 h3 = *(const uint4*)(xl + (size_t)s3 * DH + lane * 8);

        float v0[8], v1[8], v2[8], v3[8];
        float p0 = warp_sum(score8(h0, xrv, atv, v0));
        float p1 = warp_sum(score8(h1, xrv, atv, v1));
        float p2 = warp_sum(score8(h2, xrv, atv, v2));
        float p3 = warp_sum(score8(h3, xrv, atv, v3));

        float pm = fmaxf(fmaxf(p0, p1), fmaxf(p2, p3));
        float nm = fmaxf(m_w, pm);
        float c1 = __expf(m_w - nm);
        float e0 = __expf(p0 - nm);
        float e1 = __expf(p1 - nm);
        float e2 = __expf(p2 - nm);
        float e3 = __expf(p3 - nm);
        s_w = fmaf(s_w, c1, e0 + e1 + e2 + e3);
#pragma unroll
        for (int q = 0; q < 8; ++q) {
            float t = fmaf(acc[q], c1, e0 * v0[q]);
            t = fmaf(e1, v1[q], t);
            t = fmaf(e2, v2[q], t);
            acc[q] = fmaf(e3, v3[q], t);
        }
        m_w = nm;
    }
    // remainder singles
    for (; e < end; ++e) {
        int src = g_csr_src[e];
        uint4 hv = *(const uint4*)(xl + (size_t)src * DH + lane * 8);
        float v[8];
        float p = warp_sum(score8(hv, xrv, atv, v));
        float nm = fmaxf(m_w, p);
        float c1 = __expf(m_w - nm);
        float c2 = __expf(p - nm);
        s_w = fmaf(s_w, c1, c2);
#pragma unroll
        for (int q = 0; q < 8; ++q)
            acc[q] = fmaf(acc[q], c1, c2 * v[q]);
        m_w = nm;
    }

    // finalize in-warp: max term cancels in acc/s
    float inv = 1.f / s_w;
    float4 b0 = ((const float4*)bias)[lane * 2];
    float4 b1 = ((const float4*)bias)[lane * 2 + 1];
    float r[8];
    r[0] = fmaxf(fmaf(acc[0], inv, b0.x), 0.f);
    r[1] = fmaxf(fmaf(acc[1], inv, b0.y), 0.f);
    r[2] = fmaxf(fmaf(acc[2], inv, b0.z), 0.f);
    r[3] = fmaxf(fmaf(acc[3], inv, b0.w), 0.f);
    r[4] = fmaxf(fmaf(acc[4], inv, b1.x), 0.f);
    r[5] = fmaxf(fmaf(acc[5], inv, b1.y), 0.f);
    r[6] = fmaxf(fmaf(acc[6], inv, b1.z), 0.f);
    r[7] = fmaxf(fmaf(acc[7], inv, b1.w), 0.f);

    uint4 pk;
    unsigned* pu = (unsigned*)&pk;
#pragma unroll
    for (int q = 0; q < 4; ++q) {
        __half2 hh = __floats2half2_rn(r[2 * q], r[2 * q + 1]);
        pu[q] = *(unsigned*)&hh;
    }
    *(uint4*)(out + (size_t)node * DH + lane * 8) = pk;
}

// ---------------- launch ----------------
extern "C" void kernel_launch(void* const* d_in, const int* in_sizes, int n_in,
                              void* d_out, int out_size) {
    const float* x    = (const float*)d_in[0];
    const float* W1l  = (const float*)d_in[1];
    const float* b1l  = (const float*)d_in[2];
    const float* W1r  = (const float*)d_in[3];
    const float* b1r  = (const float*)d_in[4];
    const float* att1 = (const float*)d_in[5];
    const float* bias1= (const float*)d_in[6];
    const float* W2l  = (const float*)d_in[7];
    const float* b2l  = (const float*)d_in[8];
    const float* W2r  = (const float*)d_in[9];
    const float* b2r  = (const float*)d_in[10];
    const float* att2 = (const float*)d_in[11];
    const float* bias2= (const float*)d_in[12];
    const float* Wout = (const float*)d_in[13];
    const float* bout = (const float*)d_in[14];
    const void*  ei   = d_in[15];
    float* out = (float*)d_out;

    __half *xl, *xr, *h;
    cudaGetSymbolAddress((void**)&xl, g_xl);
    cudaGetSymbolAddress((void**)&xr, g_xr);
    cudaGetSymbolAddress((void**)&h,  g_h);

    static cudaStream_t s_csr = nullptr;
    static cudaEvent_t ev_root = nullptr, ev_csr = nullptr;
    if (!s_csr) {
        cudaStreamCreateWithFlags(&s_csr, cudaStreamNonBlocking);
        cudaEventCreateWithFlags(&ev_root, cudaEventDisableTiming);
        cudaEventCreateWithFlags(&ev_csr, cudaEventDisableTiming);
    }

    // fork: CSR build on side stream, concurrent with layer-1 GEMMs
    cudaEventRecord(ev_root, 0);
    cudaStreamWaitEvent(s_csr, ev_root, 0);
    k_zero_detect<<<(Nn + 255) / 256, 256, 0, s_csr>>>((const int*)ei);
    k_hist<<<(ET + 255) / 256, 256, 0, s_csr>>>(ei);
    k_scan<<<1, 1024, 0, s_csr>>>();
    k_scatter<<<(ET + 255) / 256, 256, 0, s_csr>>>(ei);
    cudaEventRecord(ev_csr, s_csr);

    dim3 gDual(4, (Nn + 127) / 128);

    // layer 1 GEMMs (independent of CSR)
    k_gemm_dual_f32<<<gDual, 256>>>(x, W1l, b1l, xl, W1r, b1r, xr, Nn, DH, DH);

    // join before GAT
    cudaStreamWaitEvent(0, ev_csr, 0);
    k_gat_layer<<<(Nn + 7) / 8, 256>>>(xl, xr, att1, bias1, h);

    // layer 2
    k_gemm_dual_f16<<<gDual, 256>>>(h, W2l, b2l, xl, W2r, b2r, xr, Nn, DH, DH);
    k_gat_layer<<<(Nn + 7) / 8, 256>>>(xl, xr, att2, bias2, h);

    // output head + log_softmax fused
    k_head_fused<<<(Nn + 127) / 128, 256>>>(h, Wout, bout, out, Nn, DH);
}

// round 12
// speedup vs baseline: 1.1120x; 1.1120x over previous
#include <cuda_runtime.h>
#include <cuda_fp16.h>
#include <math.h>

#define Nn 10000
#define Ee 320000
#define ET (Ee + Nn)   // edges + self loops
#define DH 256
#define DOUT 64

// ---------------- device scratch (no cudaMalloc allowed) ----------------
__device__ __half g_xl[Nn * DH];
__device__ __half g_xr[Nn * DH];
__device__ __half g_h[Nn * DH];
__device__ __half g_W1l[DH * DH];   // transposed [N][K], half
__device__ __half g_W1r[DH * DH];
__device__ __half g_W2l[DH * DH];
__device__ __half g_W2r[DH * DH];
__device__ __half g_Wout[DOUT * DH];
__device__ int    g_csr_src[ET];
__device__ int    g_cnt[Nn];
__device__ int    g_row_ptr[Nn + 1];
__device__ int    g_row_off[Nn];
__device__ int    g_flag_i64[1];

// ---------------- weight prep: fp32 [K][N] -> half transposed [N][K] ----------------
__global__ __launch_bounds__(256) void k_prep_weights(
    const float* __restrict__ w1l, const float* __restrict__ w1r,
    const float* __restrict__ w2l, const float* __restrict__ w2r,
    const float* __restrict__ wout)
{
    int idx = blockIdx.x * 256 + threadIdx.x;   // 0 .. 278527
    if (idx < 4 * 65536) {
        int seg = idx >> 16;
        int local = idx & 65535;
        int k = local & 255;
        int n = local >> 8;
        const float* W = (seg == 0) ? w1l : (seg == 1) ? w1r : (seg == 2) ? w2l : w2r;
        __half* O = (seg == 0) ? g_W1l : (seg == 1) ? g_W1r : (seg == 2) ? g_W2l : g_W2r;
        O[local] = __float2half(W[k * 256 + n]);
    } else {
        int local = idx - 4 * 65536;
        if (local < DOUT * DH) {
            int k = local & 255;
            int n = local >> 8;
            g_Wout[local] = __float2half(wout[k * DOUT + n]);
        }
    }
}

// ---------------- combined zero + dtype detect ----------------
__global__ void k_zero_detect(const int* ei32) {
    int i = blockIdx.x * blockDim.x + threadIdx.x;
    if (i < Nn) g_cnt[i] = 0;
    if (i == 0) {
        int all0 = 1;
        for (int j = 0; j < 64; ++j) {
            if (ei32[2 * j + 1] != 0) { all0 = 0; break; }
        }
        g_flag_i64[0] = all0;
    }
}

// hist: 4 edges per thread, vectorized loads
__global__ void k_hist(const void* ei) {
    int q = (blockIdx.x * blockDim.x + threadIdx.x) * 4;
    if (q >= ET) return;
    int is64 = g_flag_i64[0];
    int d[4];
    if (q >= Ee) {
#pragma unroll
        for (int j = 0; j < 4; ++j) d[j] = q + j - Ee;
    } else if (is64) {
        const longlong2* p = (const longlong2*)((const long long*)ei + Ee + q);
        longlong2 v0 = p[0], v1 = p[1];
        d[0] = (int)v0.x; d[1] = (int)v0.y; d[2] = (int)v1.x; d[3] = (int)v1.y;
    } else {
        int4 v = *(const int4*)((const int*)ei + Ee + q);
        d[0] = v.x; d[1] = v.y; d[2] = v.z; d[3] = v.w;
    }
#pragma unroll
    for (int j = 0; j < 4; ++j) atomicAdd(&g_cnt[d[j]], 1);
}

// hierarchical shuffle scan: 1024 threads x 10 elems
__global__ __launch_bounds__(1024) void k_scan() {
    __shared__ int wsum[32];
    int tid = threadIdx.x;
    int lane = tid & 31, w = tid >> 5;
    int base = tid * 10;
    int c[10];
    int s = 0;
#pragma unroll
    for (int i = 0; i < 10; ++i) {
        int idx = base + i;
        c[i] = (idx < Nn) ? g_cnt[idx] : 0;
        s += c[i];
    }
    int incl = s;
#pragma unroll
    for (int o = 1; o < 32; o <<= 1) {
        int v = __shfl_up_sync(0xffffffffu, incl, o);
        if (lane >= o) incl += v;
    }
    if (lane == 31) wsum[w] = incl;
    __syncthreads();
    if (w == 0) {
        int wi = wsum[lane];
#pragma unroll
        for (int o = 1; o < 32; o <<= 1) {
            int t = __shfl_up_sync(0xffffffffu, wi, o);
            if (lane >= o) wi += t;
        }
        wsum[lane] = wi;
    }
    __syncthreads();
    int excl = incl - s + (w > 0 ? wsum[w - 1] : 0);
    int run = excl;
#pragma unroll
    for (int i = 0; i < 10; ++i) {
        int idx = base + i;
        if (idx < Nn) {
            g_row_ptr[idx] = run;
            g_row_off[idx] = run;
            run += c[i];
        }
    }
    if (tid == 0) g_row_ptr[Nn] = ET;
}

// scatter: 4 edges per thread
__global__ void k_scatter(const void* ei) {
    int q = (blockIdx.x * blockDim.x + threadIdx.x) * 4;
    if (q >= ET) return;
    int is64 = g_flag_i64[0];
    int s[4], d[4];
    if (q >= Ee) {
#pragma unroll
        for (int j = 0; j < 4; ++j) { s[j] = q + j - Ee; d[j] = s[j]; }
    } else if (is64) {
        const longlong2* ps = (const longlong2*)((const long long*)ei + q);
        const longlong2* pd = (const longlong2*)((const long long*)ei + Ee + q);
        longlong2 s0 = ps[0], s1 = ps[1], d0 = pd[0], d1 = pd[1];
        s[0] = (int)s0.x; s[1] = (int)s0.y; s[2] = (int)s1.x; s[3] = (int)s1.y;
        d[0] = (int)d0.x; d[1] = (int)d0.y; d[2] = (int)d1.x; d[3] = (int)d1.y;
    } else {
        int4 sv = *(const int4*)((const int*)ei + q);
        int4 dv = *(const int4*)((const int*)ei + Ee + q);
        s[0] = sv.x; s[1] = sv.y; s[2] = sv.z; s[3] = sv.w;
        d[0] = dv.x; d[1] = dv.y; d[2] = dv.z; d[3] = dv.w;
    }
#pragma unroll
    for (int j = 0; j < 4; ++j) {
        int pos = atomicAdd(&g_row_off[d[j]], 1);
        g_csr_src[pos] = s[j];
    }
}

// ---------------- FP16 tensor-core GEMM (m16n8k16) ----------------
// A row-major [M][K] (half or float source), B pre-transposed half [Nc][K].
// smem: As[BM][40], Bs[BN][40] halves (stride 40 -> conflict-free quads)
template<int BN, int WARPS_M, int MT, typename AT, typename OT>
__device__ __forceinline__ void gemm16_body(
    const AT* __restrict__ A, const __half* __restrict__ Bt,
    const float* __restrict__ bias, OT* __restrict__ C,
    int M, int Nc, int K, int row0, int col0)
{
    constexpr int BM = 128;
    constexpr int BK = 32;
    constexpr int NT = 4;
    constexpr int KSTR = 40;

    __shared__ __half As[BM][KSTR];
    __shared__ __half Bs[BN][KSTR];

    int tid = threadIdx.x;
    int lane = tid & 31;
    int wid = tid >> 5;
    int gid = lane >> 2;
    int tin = lane & 3;

    int wm = wid % WARPS_M;
    int wn = wid / WARPS_M;
    int mbase = wm * (MT * 16);
    int nbase = wn * 32;

    float c[MT][NT][4];
#pragma unroll
    for (int i = 0; i < MT; ++i)
#pragma unroll
        for (int j = 0; j < NT; ++j)
#pragma unroll
            for (int q = 0; q < 4; ++q) c[i][j][q] = 0.f;

    constexpr int AIT = (BM * BK) / (8 * 256);   // uint4 passes for A = 2
    constexpr int BIT = (BN * BK) / (8 * 256);   // for B: 2 (BN=128) or 1 (BN=64)

    for (int k0 = 0; k0 < K; k0 += BK) {
        // ---- A tile ----
#pragma unroll
        for (int i = 0; i < AIT; ++i) {
            int idx = tid + i * 256;
            int r = idx >> 2;
            int c8 = (idx & 3) * 8;
            if constexpr (sizeof(AT) == 2) {
                uint4 hv = make_uint4(0u, 0u, 0u, 0u);
                if (row0 + r < M)
                    hv = *(const uint4*)((const __half*)A + (size_t)(row0 + r) * K + k0 + c8);
                *(uint4*)&As[r][c8] = hv;
            } else {
                float4 v0 = make_float4(0.f, 0.f, 0.f, 0.f), v1 = v0;
                if (row0 + r < M) {
                    const float* src = (const float*)A + (size_t)(row0 + r) * K + k0 + c8;
                    v0 = *(const float4*)src;
                    v1 = *(const float4*)(src + 4);
                }
                uint4 hv;
                unsigned* hu = (unsigned*)&hv;
                __half2 t;
                t = __floats2half2_rn(v0.x, v0.y); hu[0] = *(unsigned*)&t;
                t = __floats2half2_rn(v0.z, v0.w); hu[1] = *(unsigned*)&t;
                t = __floats2half2_rn(v1.x, v1.y); hu[2] = *(unsigned*)&t;
                t = __floats2half2_rn(v1.z, v1.w); hu[3] = *(unsigned*)&t;
                *(uint4*)&As[r][c8] = hv;
            }
        }
        // ---- B tile (pre-transposed half, k contiguous) ----
#pragma unroll
        for (int i = 0; i < BIT; ++i) {
            int idx = tid + i * 256;
            int n = idx >> 2;
            int c8 = (idx & 3) * 8;
            uint4 hv = *(const uint4*)(Bt + (size_t)(col0 + n) * K + k0 + c8);
            *(uint4*)&Bs[n][c8] = hv;
        }
        __syncthreads();

#pragma unroll
        for (int kk = 0; kk < BK; kk += 16) {
            unsigned a[MT][4];
#pragma unroll
            for (int mt = 0; mt < MT; ++mt) {
                int r = mbase + mt * 16 + gid;
                a[mt][0] = *(const unsigned*)&As[r][kk + 2 * tin];
                a[mt][1] = *(const unsigned*)&As[r + 8][kk + 2 * tin];
                a[mt][2] = *(const unsigned*)&As[r][kk + 8 + 2 * tin];
                a[mt][3] = *(const unsigned*)&As[r + 8][kk + 8 + 2 * tin];
            }
            unsigned b[NT][2];
#pragma unroll
            for (int nt = 0; nt < NT; ++nt) {
                int n = nbase + nt * 8 + gid;
                b[nt][0] = *(const unsigned*)&Bs[n][kk + 2 * tin];
                b[nt][1] = *(const unsigned*)&Bs[n][kk + 8 + 2 * tin];
            }
#pragma unroll
            for (int mt = 0; mt < MT; ++mt)
#pragma unroll
                for (int nt = 0; nt < NT; ++nt) {
                    asm volatile(
                        "mma.sync.aligned.m16n8k16.row.col.f32.f16.f16.f32 "
                        "{%0,%1,%2,%3}, {%4,%5,%6,%7}, {%8,%9}, {%0,%1,%2,%3};\n"
                        : "+f"(c[mt][nt][0]), "+f"(c[mt][nt][1]),
                          "+f"(c[mt][nt][2]), "+f"(c[mt][nt][3])
                        : "r"(a[mt][0]), "r"(a[mt][1]), "r"(a[mt][2]), "r"(a[mt][3]),
                          "r"(b[nt][0]), "r"(b[nt][1]));
                }
        }
        __syncthreads();
    }

#pragma unroll
    for (int mt = 0; mt < MT; ++mt) {
        int r0 = row0 + mbase + mt * 16 + gid;
        int r1 = r0 + 8;
#pragma unroll
        for (int nt = 0; nt < NT; ++nt) {
            int col = col0 + nbase + nt * 8 + tin * 2;
            float b0 = bias[col], b1 = bias[col + 1];
            if (r0 < M) {
                float v0 = c[mt][nt][0] + b0, v1 = c[mt][nt][1] + b1;
                if constexpr (sizeof(OT) == 2)
                    *(__half2*)((__half*)C + (size_t)r0 * Nc + col) = __floats2half2_rn(v0, v1);
                else
                    *(float2*)((float*)C + (size_t)r0 * Nc + col) = make_float2(v0, v1);
            }
            if (r1 < M) {
                float v0 = c[mt][nt][2] + b0, v1 = c[mt][nt][3] + b1;
                if constexpr (sizeof(OT) == 2)
                    *(__half2*)((__half*)C + (size_t)r1 * Nc + col) = __floats2half2_rn(v0, v1);
                else
                    *(float2*)((float*)C + (size_t)r1 * Nc + col) = make_float2(v0, v1);
            }
        }
    }
}

__global__ __launch_bounds__(256) void k_gemm_dual_f32(
    const float* __restrict__ A,
    const __half* __restrict__ Btl, const float* __restrict__ biasl, __half* __restrict__ Cl,
    const __half* __restrict__ Btr, const float* __restrict__ biasr, __half* __restrict__ Cr,
    int M, int Nc, int K)
{
    int sel = blockIdx.x >> 1;
    int bx = blockIdx.x & 1;
    gemm16_body<128, 2, 4, float, __half>(A, sel ? Btr : Btl, sel ? biasr : biasl,
                                          sel ? Cr : Cl, M, Nc, K,
                                          blockIdx.y * 128, bx * 128);
}

__global__ __launch_bounds__(256) void k_gemm_dual_f16(
    const __half* __restrict__ A,
    const __half* __restrict__ Btl, const float* __restrict__ biasl, __half* __restrict__ Cl,
    const __half* __restrict__ Btr, const float* __restrict__ biasr, __half* __restrict__ Cr,
    int M, int Nc, int K)
{
    int sel = blockIdx.x >> 1;
    int bx = blockIdx.x & 1;
    gemm16_body<128, 2, 4, __half, __half>(A, sel ? Btr : Btl, sel ? biasr : biasl,
                                           sel ? Cr : Cl, M, Nc, K,
                                           blockIdx.y * 128, bx * 128);
}

// ---------------- head GEMM (fp16) fused with log_softmax ----------------
__global__ __launch_bounds__(256) void k_head_fused(
    const __half* __restrict__ A, const __half* __restrict__ Bt,
    const float* __restrict__ bias, float* __restrict__ out, int M, int K)
{
    constexpr int BM = 128, BK = 32, BN = 64;
    constexpr int WARPS_M = 4, MT = 2, NT = 4;
    constexpr int KSTR = 40, LSTR = 66;

    __shared__ __half As[BM][KSTR];
    __shared__ __half Bs[BN][KSTR];
    __shared__ float s_logits[BM * LSTR];

    int tid = threadIdx.x;
    int lane = tid & 31;
    int wid = tid >> 5;
    int gid = lane >> 2;
    int tin = lane & 3;

    int wm = wid % WARPS_M;
    int wn = wid / WARPS_M;
    int mbase = wm * (MT * 16);
    int nbase = wn * 32;
    int row0 = blockIdx.x * BM;

    float c[MT][NT][4];
#pragma unroll
    for (int i = 0; i < MT; ++i)
#pragma unroll
        for (int j = 0; j < NT; ++j)
#pragma unroll
            for (int q = 0; q < 4; ++q) c[i][j][q] = 0.f;

    for (int k0 = 0; k0 < K; k0 += BK) {
#pragma unroll
        for (int i = 0; i < 2; ++i) {
            int idx = tid + i * 256;
            int r = idx >> 2;
            int c8 = (idx & 3) * 8;
            uint4 hv = make_uint4(0u, 0u, 0u, 0u);
            if (row0 + r < M)
                hv = *(const uint4*)(A + (size_t)(row0 + r) * K + k0 + c8);
            *(uint4*)&As[r][c8] = hv;
        }
        {
            int idx = tid;
            int n = idx >> 2;
            int c8 = (idx & 3) * 8;
            uint4 hv = *(const uint4*)(Bt + (size_t)n * K + k0 + c8);
            *(uint4*)&Bs[n][c8] = hv;
        }
        __syncthreads();

#pragma unroll
        for (int kk = 0; kk < BK; kk += 16) {
            unsigned a[MT][4];
#pragma unroll
            for (int mt = 0; mt < MT; ++mt) {
                int r = mbase + mt * 16 + gid;
                a[mt][0] = *(const unsigned*)&As[r][kk + 2 * tin];
                a[mt][1] = *(const unsigned*)&As[r + 8][kk + 2 * tin];
                a[mt][2] = *(const unsigned*)&As[r][kk + 8 + 2 * tin];
                a[mt][3] = *(const unsigned*)&As[r + 8][kk + 8 + 2 * tin];
            }
            unsigned b[NT][2];
#pragma unroll
            for (int nt = 0; nt < NT; ++nt) {
                int n = nbase + nt * 8 + gid;
                b[nt][0] = *(const unsigned*)&Bs[n][kk + 2 * tin];
                b[nt][1] = *(const unsigned*)&Bs[n][kk + 8 + 2 * tin];
            }
#pragma unroll
            for (int mt = 0; mt < MT; ++mt)
#pragma unroll
                for (int nt = 0; nt < NT; ++nt) {
                    asm volatile(
                        "mma.sync.aligned.m16n8k16.row.col.f32.f16.f16.f32 "
                        "{%0,%1,%2,%3}, {%4,%5,%6,%7}, {%8,%9}, {%0,%1,%2,%3};\n"
                        : "+f"(c[mt][nt][0]), "+f"(c[mt][nt][1]),
                          "+f"(c[mt][nt][2]), "+f"(c[mt][nt][3])
                        : "r"(a[mt][0]), "r"(a[mt][1]), "r"(a[mt][2]), "r"(a[mt][3]),
                          "r"(b[nt][0]), "r"(b[nt][1]));
                }
        }
        __syncthreads();
    }

#pragma unroll
    for (int mt = 0; mt < MT; ++mt) {
        int r0 = mbase + mt * 16 + gid;
        int r1 = r0 + 8;
#pragma unroll
        for (int nt = 0; nt < NT; ++nt) {
            int col = nbase + nt * 8 + tin * 2;
            float b0 = bias[col], b1 = bias[col + 1];
            *(float2*)&s_logits[r0 * LSTR + col] =
                make_float2(c[mt][nt][0] + b0, c[mt][nt][1] + b1);
            *(float2*)&s_logits[r1 * LSTR + col] =
                make_float2(c[mt][nt][2] + b0, c[mt][nt][3] + b1);
        }
    }
    __syncthreads();

    for (int r = wid * 16; r < wid * 16 + 16; ++r) {
        int node = row0 + r;
        if (node >= M) break;
        float v0 = s_logits[r * LSTR + lane];
        float v1 = s_logits[r * LSTR + 32 + lane];
        float m = fmaxf(v0, v1);
#pragma unroll
        for (int o = 16; o > 0; o >>= 1)
            m = fmaxf(m, __shfl_xor_sync(0xffffffffu, m, o));
        float s = expf(v0 - m) + expf(v1 - m);
#pragma unroll
        for (int o = 16; o > 0; o >>= 1)
            s += __shfl_xor_sync(0xffffffffu, s, o);
        float lse = m + logf(s);
        out[(size_t)node * DOUT + lane]      = v0 - lse;
        out[(size_t)node * DOUT + 32 + lane] = v1 - lse;
    }
}

// ---------------- GATv2 layer: warp-per-node, chunked gather ----------------
__device__ __forceinline__ float warp_sum(float v) {
#pragma unroll
    for (int o = 16; o > 0; o >>= 1) v += __shfl_xor_sync(0xffffffffu, v, o);
    return v;
}

__device__ __forceinline__ float lrelu(float v) {
    return (v > 0.f) ? v : 0.2f * v;
}

__device__ __forceinline__ float score8(uint4 hv, const float* xrv, const float* atv,
                                        float* vout) {
    const unsigned* hu = (const unsigned*)&hv;
    float p = 0.f;
#pragma unroll
    for (int q = 0; q < 4; ++q) {
        float2 t = __half22float2(*(const __half2*)&hu[q]);
        vout[2 * q] = t.x; vout[2 * q + 1] = t.y;
        p = fmaf(atv[2 * q],     lrelu(t.x + xrv[2 * q]),     p);
        p = fmaf(atv[2 * q + 1], lrelu(t.y + xrv[2 * q + 1]), p);
    }
    return p;
}

__global__ __launch_bounds__(256) void k_gat_layer(
    const __half* __restrict__ xl, const __half* __restrict__ xr,
    const float* __restrict__ att, const float* __restrict__ bias,
    __half* __restrict__ out)
{
    int lane = threadIdx.x & 31;
    int w = threadIdx.x >> 5;
    int node = blockIdx.x * 8 + w;
    if (node >= Nn) return;

    float xrv[8], atv[8];
    {
        uint4 hx = *(const uint4*)(xr + (size_t)node * DH + lane * 8);
        const unsigned* hu = (const unsigned*)&hx;
#pragma unroll
        for (int q = 0; q < 4; ++q) {
            float2 p = __half22float2(*(const __half2*)&hu[q]);
            xrv[2 * q] = p.x; xrv[2 * q + 1] = p.y;
        }
        float4 a0 = ((const float4*)att)[lane * 2];
        float4 a1 = ((const float4*)att)[lane * 2 + 1];
        atv[0] = a0.x; atv[1] = a0.y; atv[2] = a0.z; atv[3] = a0.w;
        atv[4] = a1.x; atv[5] = a1.y; atv[6] = a1.z; atv[7] = a1.w;
    }

    int beg = g_row_ptr[node];
    int end = g_row_ptr[node + 1];

    float m_w = -INFINITY, s_w = 0.f;
    float acc[8] = {0.f, 0.f, 0.f, 0.f, 0.f, 0.f, 0.f, 0.f};

    int e = beg;
    for (; e + 4 <= end; e += 4) {
        int s0 = g_csr_src[e];
        int s1 = g_csr_src[e + 1];
        int s2 = g_csr_src[e + 2];
        int s3 = g_csr_src[e + 3];
        uint4 h0 = *(const uint4*)(xl + (size_t)s0 * DH + lane * 8);
        uint4 h1 = *(const uint4*)(xl + (size_t)s1 * DH + lane * 8);
        uint4 h2 = *(const uint4*)(xl + (size_t)s2 * DH + lane * 8);
        uint4 h3 = *(const uint4*)(xl + (size_t)s3 * DH + lane * 8);

        float v0[8], v1[8], v2[8], v3[8];
        float p0 = warp_sum(score8(h0, xrv, atv, v0));
        float p1 = warp_sum(score8(h1, xrv, atv, v1));
        float p2 = warp_sum(score8(h2, xrv, atv, v2));
        float p3 = warp_sum(score8(h3, xrv, atv, v3));

        float pm = fmaxf(fmaxf(p0, p1), fmaxf(p2, p3));
        float nm = fmaxf(m_w, pm);
        float c1 = __expf(m_w - nm);
        float e0 = __expf(p0 - nm);
        float e1 = __expf(p1 - nm);
        float e2 = __expf(p2 - nm);
        float e3 = __expf(p3 - nm);
        s_w = fmaf(s_w, c1, e0 + e1 + e2 + e3);
#pragma unroll
        for (int q = 0; q < 8; ++q) {
            float t = fmaf(acc[q], c1, e0 * v0[q]);
            t = fmaf(e1, v1[q], t);
            t = fmaf(e2, v2[q], t);
            acc[q] = fmaf(e3, v3[q], t);
        }
        m_w = nm;
    }
    for (; e < end; ++e) {
        int src = g_csr_src[e];
        uint4 hv = *(const uint4*)(xl + (size_t)src * DH + lane * 8);
        float v[8];
        float p = warp_sum(score8(hv, xrv, atv, v));
        float nm = fmaxf(m_w, p);
        float c1 = __expf(m_w - nm);
        float c2 = __expf(p - nm);
        s_w = fmaf(s_w, c1, c2);
#pragma unroll
        for (int q = 0; q < 8; ++q)
            acc[q] = fmaf(acc[q], c1, c2 * v[q]);
        m_w = nm;
    }

    float inv = 1.f / s_w;
    float4 b0 = ((const float4*)bias)[lane * 2];
    float4 b1 = ((const float4*)bias)[lane * 2 + 1];
    float r[8];
    r[0] = fmaxf(fmaf(acc[0], inv, b0.x), 0.f);
    r[1] = fmaxf(fmaf(acc[1], inv, b0.y), 0.f);
    r[2] = fmaxf(fmaf(acc[2], inv, b0.z), 0.f);
    r[3] = fmaxf(fmaf(acc[3], inv, b0.w), 0.f);
    r[4] = fmaxf(fmaf(acc[4], inv, b1.x), 0.f);
    r[5] = fmaxf(fmaf(acc[5], inv, b1.y), 0.f);
    r[6] = fmaxf(fmaf(acc[6], inv, b1.z), 0.f);
    r[7] = fmaxf(fmaf(acc[7], inv, b1.w), 0.f);

    uint4 pk;
    unsigned* pu = (unsigned*)&pk;
#pragma unroll
    for (int q = 0; q < 4; ++q) {
        __half2 hh = __floats2half2_rn(r[2 * q], r[2 * q + 1]);
        pu[q] = *(unsigned*)&hh;
    }
    *(uint4*)(out + (size_t)node * DH + lane * 8) = pk;
}

// ---------------- launch ----------------
extern "C" void kernel_launch(void* const* d_in, const int* in_sizes, int n_in,
                              void* d_out, int out_size) {
    const float* x    = (const float*)d_in[0];
    const float* W1l  = (const float*)d_in[1];
    const float* b1l  = (const float*)d_in[2];
    const float* W1r  = (const float*)d_in[3];
    const float* b1r  = (const float*)d_in[4];
    const float* att1 = (const float*)d_in[5];
    const float* bias1= (const float*)d_in[6];
    const float* W2l  = (const float*)d_in[7];
    const float* b2l  = (const float*)d_in[8];
    const float* W2r  = (const float*)d_in[9];
    const float* b2r  = (const float*)d_in[10];
    const float* att2 = (const float*)d_in[11];
    const float* bias2= (const float*)d_in[12];
    const float* Wout = (const float*)d_in[13];
    const float* bout = (const float*)d_in[14];
    const void*  ei   = d_in[15];
    float* out = (float*)d_out;

    __half *xl, *xr, *h, *w1l, *w1r, *w2l, *w2r, *wo;
    cudaGetSymbolAddress((void**)&xl, g_xl);
    cudaGetSymbolAddress((void**)&xr, g_xr);
    cudaGetSymbolAddress((void**)&h,  g_h);
    cudaGetSymbolAddress((void**)&w1l, g_W1l);
    cudaGetSymbolAddress((void**)&w1r, g_W1r);
    cudaGetSymbolAddress((void**)&w2l, g_W2l);
    cudaGetSymbolAddress((void**)&w2r, g_W2r);
    cudaGetSymbolAddress((void**)&wo,  g_Wout);

    static cudaStream_t s_csr = nullptr;
    static cudaEvent_t ev_root = nullptr, ev_csr = nullptr;
    if (!s_csr) {
        cudaStreamCreateWithFlags(&s_csr, cudaStreamNonBlocking);
        cudaEventCreateWithFlags(&ev_root, cudaEventDisableTiming);
        cudaEventCreateWithFlags(&ev_csr, cudaEventDisableTiming);
    }

    // fork: CSR build on side stream
    cudaEventRecord(ev_root, 0);
    cudaStreamWaitEvent(s_csr, ev_root, 0);
    k_zero_detect<<<(Nn + 255) / 256, 256, 0, s_csr>>>((const int*)ei);
    k_hist<<<(ET / 4 + 255) / 256, 256, 0, s_csr>>>(ei);
    k_scan<<<1, 1024, 0, s_csr>>>();
    k_scatter<<<(ET / 4 + 255) / 256, 256, 0, s_csr>>>(ei);
    cudaEventRecord(ev_csr, s_csr);

    // main: weight prep then layer-1 GEMMs
    k_prep_weights<<<(4 * 65536 + DOUT * DH + 255) / 256, 256>>>(W1l, W1r, W2l, W2r, Wout);

    dim3 gDual(4, (Nn + 127) / 128);
    k_gemm_dual_f32<<<gDual, 256>>>(x, w1l, b1l, xl, w1r, b1r, xr, Nn, DH, DH);

    // join before GAT
    cudaStreamWaitEvent(0, ev_csr, 0);
    k_gat_layer<<<(Nn + 7) / 8, 256>>>(xl, xr, att1, bias1, h);

    // layer 2
    k_gemm_dual_f16<<<gDual, 256>>>(h, w2l, b2l, xl, w2r, b2r, xr, Nn, DH, DH);
    k_gat_layer<<<(Nn + 7) / 8, 256>>>(xl, xr, att2, bias2, h);

    // output head + log_softmax fused
    k_head_fused<<<(Nn + 127) / 128, 256>>>(h, wo, bout, out, Nn, DH);
}

// round 13
// speedup vs baseline: 1.1171x; 1.0046x over previous
#include <cuda_runtime.h>
#include <cuda_fp16.h>
#include <math.h>

#define Nn 10000
#define Ee 320000
#define ET (Ee + Nn)   // edges + self loops
#define DH 256
#define DOUT 64

// ---------------- device scratch (no cudaMalloc allowed) ----------------
__device__ __half g_xl[Nn * DH];
__device__ __half g_xr[Nn * DH];
__device__ __half g_h[Nn * DH];
__device__ __half g_W1l[DH * DH];   // transposed [N][K], half
__device__ __half g_W1r[DH * DH];
__device__ __half g_W2l[DH * DH];
__device__ __half g_W2r[DH * DH];
__device__ __half g_Wout[DOUT * DH];
__device__ int    g_csr_src[ET];
__device__ int    g_cnt[Nn];
__device__ int    g_row_ptr[Nn + 1];
__device__ int    g_row_off[Nn];
__device__ int    g_flag_i64[1];

// ---------------- weight prep: fp32 [K][N] -> half transposed [N][K] ----------------
__global__ __launch_bounds__(256) void k_prep_weights(
    const float* __restrict__ w1l, const float* __restrict__ w1r,
    const float* __restrict__ w2l, const float* __restrict__ w2r,
    const float* __restrict__ wout)
{
    int idx = blockIdx.x * 256 + threadIdx.x;   // 0 .. 278527
    if (idx < 4 * 65536) {
        int seg = idx >> 16;
        int local = idx & 65535;
        int k = local & 255;
        int n = local >> 8;
        const float* W = (seg == 0) ? w1l : (seg == 1) ? w1r : (seg == 2) ? w2l : w2r;
        __half* O = (seg == 0) ? g_W1l : (seg == 1) ? g_W1r : (seg == 2) ? g_W2l : g_W2r;
        O[local] = __float2half(W[k * 256 + n]);
    } else {
        int local = idx - 4 * 65536;
        if (local < DOUT * DH) {
            int k = local & 255;
            int n = local >> 8;
            g_Wout[local] = __float2half(wout[k * DOUT + n]);
        }
    }
}

// ---------------- combined zero + dtype detect ----------------
__global__ void k_zero_detect(const int* ei32) {
    int i = blockIdx.x * blockDim.x + threadIdx.x;
    if (i < Nn) g_cnt[i] = 0;
    if (i == 0) {
        int all0 = 1;
        for (int j = 0; j < 64; ++j) {
            if (ei32[2 * j + 1] != 0) { all0 = 0; break; }
        }
        g_flag_i64[0] = all0;
    }
}

// hist: 4 edges per thread, vectorized loads
__global__ void k_hist(const void* ei) {
    int q = (blockIdx.x * blockDim.x + threadIdx.x) * 4;
    if (q >= ET) return;
    int is64 = g_flag_i64[0];
    int d[4];
    if (q >= Ee) {
#pragma unroll
        for (int j = 0; j < 4; ++j) d[j] = q + j - Ee;
    } else if (is64) {
        const longlong2* p = (const longlong2*)((const long long*)ei + Ee + q);
        longlong2 v0 = p[0], v1 = p[1];
        d[0] = (int)v0.x; d[1] = (int)v0.y; d[2] = (int)v1.x; d[3] = (int)v1.y;
    } else {
        int4 v = *(const int4*)((const int*)ei + Ee + q);
        d[0] = v.x; d[1] = v.y; d[2] = v.z; d[3] = v.w;
    }
#pragma unroll
    for (int j = 0; j < 4; ++j) atomicAdd(&g_cnt[d[j]], 1);
}

// hierarchical shuffle scan: 1024 threads x 10 elems
__global__ __launch_bounds__(1024) void k_scan() {
    __shared__ int wsum[32];
    int tid = threadIdx.x;
    int lane = tid & 31, w = tid >> 5;
    int base = tid * 10;
    int c[10];
    int s = 0;
#pragma unroll
    for (int i = 0; i < 10; ++i) {
        int idx = base + i;
        c[i] = (idx < Nn) ? g_cnt[idx] : 0;
        s += c[i];
    }
    int incl = s;
#pragma unroll
    for (int o = 1; o < 32; o <<= 1) {
        int v = __shfl_up_sync(0xffffffffu, incl, o);
        if (lane >= o) incl += v;
    }
    if (lane == 31) wsum[w] = incl;
    __syncthreads();
    if (w == 0) {
        int wi = wsum[lane];
#pragma unroll
        for (int o = 1; o < 32; o <<= 1) {
            int t = __shfl_up_sync(0xffffffffu, wi, o);
            if (lane >= o) wi += t;
        }
        wsum[lane] = wi;
    }
    __syncthreads();
    int excl = incl - s + (w > 0 ? wsum[w - 1] : 0);
    int run = excl;
#pragma unroll
    for (int i = 0; i < 10; ++i) {
        int idx = base + i;
        if (idx < Nn) {
            g_row_ptr[idx] = run;
            g_row_off[idx] = run;
            run += c[i];
        }
    }
    if (tid == 0) g_row_ptr[Nn] = ET;
}

// scatter: 4 edges per thread
__global__ void k_scatter(const void* ei) {
    int q = (blockIdx.x * blockDim.x + threadIdx.x) * 4;
    if (q >= ET) return;
    int is64 = g_flag_i64[0];
    int s[4], d[4];
    if (q >= Ee) {
#pragma unroll
        for (int j = 0; j < 4; ++j) { s[j] = q + j - Ee; d[j] = s[j]; }
    } else if (is64) {
        const longlong2* ps = (const longlong2*)((const long long*)ei + q);
        const longlong2* pd = (const longlong2*)((const long long*)ei + Ee + q);
        longlong2 s0 = ps[0], s1 = ps[1], d0 = pd[0], d1 = pd[1];
        s[0] = (int)s0.x; s[1] = (int)s0.y; s[2] = (int)s1.x; s[3] = (int)s1.y;
        d[0] = (int)d0.x; d[1] = (int)d0.y; d[2] = (int)d1.x; d[3] = (int)d1.y;
    } else {
        int4 sv = *(const int4*)((const int*)ei + q);
        int4 dv = *(const int4*)((const int*)ei + Ee + q);
        s[0] = sv.x; s[1] = sv.y; s[2] = sv.z; s[3] = sv.w;
        d[0] = dv.x; d[1] = dv.y; d[2] = dv.z; d[3] = dv.w;
    }
#pragma unroll
    for (int j = 0; j < 4; ++j) {
        int pos = atomicAdd(&g_row_off[d[j]], 1);
        g_csr_src[pos] = s[j];
    }
}

// ---------------- FP16 tensor-core GEMM (m16n8k16) ----------------
// A row-major [M][K] (half or float source), B pre-transposed half [Nc][K].
// smem: As[BM][40], Bs[BN][40] halves (stride 40 -> conflict-free quads)
template<int BN, int WARPS_M, int MT, typename AT, typename OT>
__device__ __forceinline__ void gemm16_body(
    const AT* __restrict__ A, const __half* __restrict__ Bt,
    const float* __restrict__ bias, OT* __restrict__ C,
    int M, int Nc, int K, int row0, int col0)
{
    constexpr int BM = 128;
    constexpr int BK = 32;
    constexpr int NT = 4;
    constexpr int KSTR = 40;

    __shared__ __half As[BM][KSTR];
    __shared__ __half Bs[BN][KSTR];

    int tid = threadIdx.x;
    int lane = tid & 31;
    int wid = tid >> 5;
    int gid = lane >> 2;
    int tin = lane & 3;

    int wm = wid % WARPS_M;
    int wn = wid / WARPS_M;
    int mbase = wm * (MT * 16);
    int nbase = wn * 32;

    float c[MT][NT][4];
#pragma unroll
    for (int i = 0; i < MT; ++i)
#pragma unroll
        for (int j = 0; j < NT; ++j)
#pragma unroll
            for (int q = 0; q < 4; ++q) c[i][j][q] = 0.f;

    constexpr int AIT = (BM * BK) / (8 * 256);   // uint4 passes for A = 2
    constexpr int BIT = (BN * BK) / (8 * 256);   // for B: 2 (BN=128) or 1 (BN=64)

    for (int k0 = 0; k0 < K; k0 += BK) {
        // ---- A tile ----
#pragma unroll
        for (int i = 0; i < AIT; ++i) {
            int idx = tid + i * 256;
            int r = idx >> 2;
            int c8 = (idx & 3) * 8;
            if constexpr (sizeof(AT) == 2) {
                uint4 hv = make_uint4(0u, 0u, 0u, 0u);
                if (row0 + r < M)
                    hv = *(const uint4*)((const __half*)A + (size_t)(row0 + r) * K + k0 + c8);
                *(uint4*)&As[r][c8] = hv;
            } else {
                float4 v0 = make_float4(0.f, 0.f, 0.f, 0.f), v1 = v0;
                if (row0 + r < M) {
                    const float* src = (const float*)A + (size_t)(row0 + r) * K + k0 + c8;
                    v0 = *(const float4*)src;
                    v1 = *(const float4*)(src + 4);
                }
                uint4 hv;
                unsigned* hu = (unsigned*)&hv;
                __half2 t;
                t = __floats2half2_rn(v0.x, v0.y); hu[0] = *(unsigned*)&t;
                t = __floats2half2_rn(v0.z, v0.w); hu[1] = *(unsigned*)&t;
                t = __floats2half2_rn(v1.x, v1.y); hu[2] = *(unsigned*)&t;
                t = __floats2half2_rn(v1.z, v1.w); hu[3] = *(unsigned*)&t;
                *(uint4*)&As[r][c8] = hv;
            }
        }
        // ---- B tile (pre-transposed half, k contiguous) ----
#pragma unroll
        for (int i = 0; i < BIT; ++i) {
            int idx = tid + i * 256;
            int n = idx >> 2;
            int c8 = (idx & 3) * 8;
            uint4 hv = *(const uint4*)(Bt + (size_t)(col0 + n) * K + k0 + c8);
            *(uint4*)&Bs[n][c8] = hv;
        }
        __syncthreads();

#pragma unroll
        for (int kk = 0; kk < BK; kk += 16) {
            unsigned a[MT][4];
#pragma unroll
            for (int mt = 0; mt < MT; ++mt) {
                int r = mbase + mt * 16 + gid;
                a[mt][0] = *(const unsigned*)&As[r][kk + 2 * tin];
                a[mt][1] = *(const unsigned*)&As[r + 8][kk + 2 * tin];
                a[mt][2] = *(const unsigned*)&As[r][kk + 8 + 2 * tin];
                a[mt][3] = *(const unsigned*)&As[r + 8][kk + 8 + 2 * tin];
            }
            unsigned b[NT][2];
#pragma unroll
            for (int nt = 0; nt < NT; ++nt) {
                int n = nbase + nt * 8 + gid;
                b[nt][0] = *(const unsigned*)&Bs[n][kk + 2 * tin];
                b[nt][1] = *(const unsigned*)&Bs[n][kk + 8 + 2 * tin];
            }
#pragma unroll
            for (int mt = 0; mt < MT; ++mt)
#pragma unroll
                for (int nt = 0; nt < NT; ++nt) {
                    asm volatile(
                        "mma.sync.aligned.m16n8k16.row.col.f32.f16.f16.f32 "
                        "{%0,%1,%2,%3}, {%4,%5,%6,%7}, {%8,%9}, {%0,%1,%2,%3};\n"
                        : "+f"(c[mt][nt][0]), "+f"(c[mt][nt][1]),
                          "+f"(c[mt][nt][2]), "+f"(c[mt][nt][3])
                        : "r"(a[mt][0]), "r"(a[mt][1]), "r"(a[mt][2]), "r"(a[mt][3]),
                          "r"(b[nt][0]), "r"(b[nt][1]));
                }
        }
        __syncthreads();
    }

#pragma unroll
    for (int mt = 0; mt < MT; ++mt) {
        int r0 = row0 + mbase + mt * 16 + gid;
        int r1 = r0 + 8;
#pragma unroll
        for (int nt = 0; nt < NT; ++nt) {
            int col = col0 + nbase + nt * 8 + tin * 2;
            float b0 = bias[col], b1 = bias[col + 1];
            if (r0 < M) {
                float v0 = c[mt][nt][0] + b0, v1 = c[mt][nt][1] + b1;
                if constexpr (sizeof(OT) == 2)
                    *(__half2*)((__half*)C + (size_t)r0 * Nc + col) = __floats2half2_rn(v0, v1);
                else
                    *(float2*)((float*)C + (size_t)r0 * Nc + col) = make_float2(v0, v1);
            }
            if (r1 < M) {
                float v0 = c[mt][nt][2] + b0, v1 = c[mt][nt][3] + b1;
                if constexpr (sizeof(OT) == 2)
                    *(__half2*)((__half*)C + (size_t)r1 * Nc + col) = __floats2half2_rn(v0, v1);
                else
                    *(float2*)((float*)C + (size_t)r1 * Nc + col) = make_float2(v0, v1);
            }
        }
    }
}

__global__ __launch_bounds__(256) void k_gemm_dual_f32(
    const float* __restrict__ A,
    const __half* __restrict__ Btl, const float* __restrict__ biasl, __half* __restrict__ Cl,
    const __half* __restrict__ Btr, const float* __restrict__ biasr, __half* __restrict__ Cr,
    int M, int Nc, int K)
{
    int sel = blockIdx.x >> 1;
    int bx = blockIdx.x & 1;
    gemm16_body<128, 2, 4, float, __half>(A, sel ? Btr : Btl, sel ? biasr : biasl,
                                          sel ? Cr : Cl, M, Nc, K,
                                          blockIdx.y * 128, bx * 128);
}

__global__ __launch_bounds__(256) void k_gemm_dual_f16(
    const __half* __restrict__ A,
    const __half* __restrict__ Btl, const float* __restrict__ biasl, __half* __restrict__ Cl,
    const __half* __restrict__ Btr, const float* __restrict__ biasr, __half* __restrict__ Cr,
    int M, int Nc, int K)
{
    int sel = blockIdx.x >> 1;
    int bx = blockIdx.x & 1;
    gemm16_body<128, 2, 4, __half, __half>(A, sel ? Btr : Btl, sel ? biasr : biasl,
                                           sel ? Cr : Cl, M, Nc, K,
                                           blockIdx.y * 128, bx * 128);
}

// ---------------- head GEMM (fp16) fused with log_softmax ----------------
__global__ __launch_bounds__(256) void k_head_fused(
    const __half* __restrict__ A, const __half* __restrict__ Bt,
    const float* __restrict__ bias, float* __restrict__ out, int M, int K)
{
    constexpr int BM = 128, BK = 32, BN = 64;
    constexpr int WARPS_M = 4, MT = 2, NT = 4;
    constexpr int KSTR = 40, LSTR = 66;

    __shared__ __half As[BM][KSTR];
    __shared__ __half Bs[BN][KSTR];
    __shared__ float s_logits[BM * LSTR];

    int tid = threadIdx.x;
    int lane = tid & 31;
    int wid = tid >> 5;
    int gid = lane >> 2;
    int tin = lane & 3;

    int wm = wid % WARPS_M;
    int wn = wid / WARPS_M;
    int mbase = wm * (MT * 16);
    int nbase = wn * 32;
    int row0 = blockIdx.x * BM;

    float c[MT][NT][4];
#pragma unroll
    for (int i = 0; i < MT; ++i)
#pragma unroll
        for (int j = 0; j < NT; ++j)
#pragma unroll
            for (int q = 0; q < 4; ++q) c[i][j][q] = 0.f;

    for (int k0 = 0; k0 < K; k0 += BK) {
#pragma unroll
        for (int i = 0; i < 2; ++i) {
            int idx = tid + i * 256;
            int r = idx >> 2;
            int c8 = (idx & 3) * 8;
            uint4 hv = make_uint4(0u, 0u, 0u, 0u);
            if (row0 + r < M)
                hv = *(const uint4*)(A + (size_t)(row0 + r) * K + k0 + c8);
            *(uint4*)&As[r][c8] = hv;
        }
        {
            int idx = tid;
            int n = idx >> 2;
            int c8 = (idx & 3) * 8;
            uint4 hv = *(const uint4*)(Bt + (size_t)n * K + k0 + c8);
            *(uint4*)&Bs[n][c8] = hv;
        }
        __syncthreads();

#pragma unroll
        for (int kk = 0; kk < BK; kk += 16) {
            unsigned a[MT][4];
#pragma unroll
            for (int mt = 0; mt < MT; ++mt) {
                int r = mbase + mt * 16 + gid;
                a[mt][0] = *(const unsigned*)&As[r][kk + 2 * tin];
                a[mt][1] = *(const unsigned*)&As[r + 8][kk + 2 * tin];
                a[mt][2] = *(const unsigned*)&As[r][kk + 8 + 2 * tin];
                a[mt][3] = *(const unsigned*)&As[r + 8][kk + 8 + 2 * tin];
            }
            unsigned b[NT][2];
#pragma unroll
            for (int nt = 0; nt < NT; ++nt) {
                int n = nbase + nt * 8 + gid;
                b[nt][0] = *(const unsigned*)&Bs[n][kk + 2 * tin];
                b[nt][1] = *(const unsigned*)&Bs[n][kk + 8 + 2 * tin];
            }
#pragma unroll
            for (int mt = 0; mt < MT; ++mt)
#pragma unroll
                for (int nt = 0; nt < NT; ++nt) {
                    asm volatile(
                        "mma.sync.aligned.m16n8k16.row.col.f32.f16.f16.f32 "
                        "{%0,%1,%2,%3}, {%4,%5,%6,%7}, {%8,%9}, {%0,%1,%2,%3};\n"
                        : "+f"(c[mt][nt][0]), "+f"(c[mt][nt][1]),
                          "+f"(c[mt][nt][2]), "+f"(c[mt][nt][3])
                        : "r"(a[mt][0]), "r"(a[mt][1]), "r"(a[mt][2]), "r"(a[mt][3]),
                          "r"(b[nt][0]), "r"(b[nt][1]));
                }
        }
        __syncthreads();
    }

#pragma unroll
    for (int mt = 0; mt < MT; ++mt) {
        int r0 = mbase + mt * 16 + gid;
        int r1 = r0 + 8;
#pragma unroll
        for (int nt = 0; nt < NT; ++nt) {
            int col = nbase + nt * 8 + tin * 2;
            float b0 = bias[col], b1 = bias[col + 1];
            *(float2*)&s_logits[r0 * LSTR + col] =
                make_float2(c[mt][nt][0] + b0, c[mt][nt][1] + b1);
            *(float2*)&s_logits[r1 * LSTR + col] =
                make_float2(c[mt][nt][2] + b0, c[mt][nt][3] + b1);
        }
    }
    __syncthreads();

    for (int r = wid * 16; r < wid * 16 + 16; ++r) {
        int node = row0 + r;
        if (node >= M) break;
        float v0 = s_logits[r * LSTR + lane];
        float v1 = s_logits[r * LSTR + 32 + lane];
        float m = fmaxf(v0, v1);
#pragma unroll
        for (int o = 16; o > 0; o >>= 1)
            m = fmaxf(m, __shfl_xor_sync(0xffffffffu, m, o));
        float s = expf(v0 - m) + expf(v1 - m);
#pragma unroll
        for (int o = 16; o > 0; o >>= 1)
            s += __shfl_xor_sync(0xffffffffu, s, o);
        float lse = m + logf(s);
        out[(size_t)node * DOUT + lane]      = v0 - lse;
        out[(size_t)node * DOUT + 32 + lane] = v1 - lse;
    }
}

// ---------------- GATv2 layer: warp-per-node, chunked gather ----------------
__device__ __forceinline__ float warp_sum(float v) {
#pragma unroll
    for (int o = 16; o > 0; o >>= 1) v += __shfl_xor_sync(0xffffffffu, v, o);
    return v;
}

__device__ __forceinline__ float lrelu(float v) {
    return (v > 0.f) ? v : 0.2f * v;
}

__device__ __forceinline__ float score8(uint4 hv, const float* xrv, const float* atv,
                                        float* vout) {
    const unsigned* hu = (const unsigned*)&hv;
    float p = 0.f;
#pragma unroll
    for (int q = 0; q < 4; ++q) {
        float2 t = __half22float2(*(const __half2*)&hu[q]);
        vout[2 * q] = t.x; vout[2 * q + 1] = t.y;
        p = fmaf(atv[2 * q],     lrelu(t.x + xrv[2 * q]),     p);
        p = fmaf(atv[2 * q + 1], lrelu(t.y + xrv[2 * q + 1]), p);
    }
    return p;
}

__global__ __launch_bounds__(256) void k_gat_layer(
    const __half* __restrict__ xl, const __half* __restrict__ xr,
    const float* __restrict__ att, const float* __restrict__ bias,
    __half* __restrict__ out)
{
    int lane = threadIdx.x & 31;
    int w = threadIdx.x >> 5;
    int node = blockIdx.x * 8 + w;
    if (node >= Nn) return;

    float xrv[8], atv[8];
    {
        uint4 hx = *(const uint4*)(xr + (size_t)node * DH + lane * 8);
        const unsigned* hu = (const unsigned*)&hx;
#pragma unroll
        for (int q = 0; q < 4; ++q) {
            float2 p = __half22float2(*(const __half2*)&hu[q]);
            xrv[2 * q] = p.x; xrv[2 * q + 1] = p.y;
        }
        float4 a0 = ((const float4*)att)[lane * 2];
        float4 a1 = ((const float4*)att)[lane * 2 + 1];
        atv[0] = a0.x; atv[1] = a0.y; atv[2] = a0.z; atv[3] = a0.w;
        atv[4] = a1.x; atv[5] = a1.y; atv[6] = a1.z; atv[7] = a1.w;
    }

    int beg = g_row_ptr[node];
    int end = g_row_ptr[node + 1];

    float m_w = -INFINITY, s_w = 0.f;
    float acc[8] = {0.f, 0.f, 0.f, 0.f, 0.f, 0.f, 0.f, 0.f};

    int e = beg;
    for (; e + 4 <= end; e += 4) {
        int s0 = g_csr_src[e];
        int s1 = g_csr_src[e + 1];
        int s2 = g_csr_src[e + 2];
        int s3 = g_csr_src[e + 3];
        uint4 h0 = *(const uint4*)(xl + (size_t)s0 * DH + lane * 8);
        uint4 h1 = *(const uint4*)(xl + (size_t)s1 * DH + lane * 8);
        uint4 h2 = *(const uint4*)(xl + (size_t)s2 * DH + lane * 8);
        uint4 h3 = *(const uint4*)(xl + (size_t)s3 * DH + lane * 8);

        float v0[8], v1[8], v2[8], v3[8];
        float p0 = warp_sum(score8(h0, xrv, atv, v0));
        float p1 = warp_sum(score8(h1, xrv, atv, v1));
        float p2 = warp_sum(score8(h2, xrv, atv, v2));
        float p3 = warp_sum(score8(h3, xrv, atv, v3));

        float pm = fmaxf(fmaxf(p0, p1), fmaxf(p2, p3));
        float nm = fmaxf(m_w, pm);
        float c1 = __expf(m_w - nm);
        float e0 = __expf(p0 - nm);
        float e1 = __expf(p1 - nm);
        float e2 = __expf(p2 - nm);
        float e3 = __expf(p3 - nm);
        s_w = fmaf(s_w, c1, e0 + e1 + e2 + e3);
#pragma unroll
        for (int q = 0; q < 8; ++q) {
            float t = fmaf(acc[q], c1, e0 * v0[q]);
            t = fmaf(e1, v1[q], t);
            t = fmaf(e2, v2[q], t);
            acc[q] = fmaf(e3, v3[q], t);
        }
        m_w = nm;
    }
    for (; e < end; ++e) {
        int src = g_csr_src[e];
        uint4 hv = *(const uint4*)(xl + (size_t)src * DH + lane * 8);
        float v[8];
        float p = warp_sum(score8(hv, xrv, atv, v));
        float nm = fmaxf(m_w, p);
        float c1 = __expf(m_w - nm);
        float c2 = __expf(p - nm);
        s_w = fmaf(s_w, c1, c2);
#pragma unroll
        for (int q = 0; q < 8; ++q)
            acc[q] = fmaf(acc[q], c1, c2 * v[q]);
        m_w = nm;
    }

    float inv = 1.f / s_w;
    float4 b0 = ((const float4*)bias)[lane * 2];
    float4 b1 = ((const float4*)bias)[lane * 2 + 1];
    float r[8];
    r[0] = fmaxf(fmaf(acc[0], inv, b0.x), 0.f);
    r[1] = fmaxf(fmaf(acc[1], inv, b0.y), 0.f);
    r[2] = fmaxf(fmaf(acc[2], inv, b0.z), 0.f);
    r[3] = fmaxf(fmaf(acc[3], inv, b0.w), 0.f);
    r[4] = fmaxf(fmaf(acc[4], inv, b1.x), 0.f);
    r[5] = fmaxf(fmaf(acc[5], inv, b1.y), 0.f);
    r[6] = fmaxf(fmaf(acc[6], inv, b1.z), 0.f);
    r[7] = fmaxf(fmaf(acc[7], inv, b1.w), 0.f);

    uint4 pk;
    unsigned* pu = (unsigned*)&pk;
#pragma unroll
    for (int q = 0; q < 4; ++q) {
        __half2 hh = __floats2half2_rn(r[2 * q], r[2 * q + 1]);
        pu[q] = *(unsigned*)&hh;
    }
    *(uint4*)(out + (size_t)node * DH + lane * 8) = pk;
}

// ---------------- launch ----------------
extern "C" void kernel_launch(void* const* d_in, const int* in_sizes, int n_in,
                              void* d_out, int out_size) {
    const float* x    = (const float*)d_in[0];
    const float* W1l  = (const float*)d_in[1];
    const float* b1l  = (const float*)d_in[2];
    const float* W1r  = (const float*)d_in[3];
    const float* b1r  = (const float*)d_in[4];
    const float* att1 = (const float*)d_in[5];
    const float* bias1= (const float*)d_in[6];
    const float* W2l  = (const float*)d_in[7];
    const float* b2l  = (const float*)d_in[8];
    const float* W2r  = (const float*)d_in[9];
    const float* b2r  = (const float*)d_in[10];
    const float* att2 = (const float*)d_in[11];
    const float* bias2= (const float*)d_in[12];
    const float* Wout = (const float*)d_in[13];
    const float* bout = (const float*)d_in[14];
    const void*  ei   = d_in[15];
    float* out = (float*)d_out;

    __half *xl, *xr, *h, *w1l, *w1r, *w2l, *w2r, *wo;
    cudaGetSymbolAddress((void**)&xl, g_xl);
    cudaGetSymbolAddress((void**)&xr, g_xr);
    cudaGetSymbolAddress((void**)&h,  g_h);
    cudaGetSymbolAddress((void**)&w1l, g_W1l);
    cudaGetSymbolAddress((void**)&w1r, g_W1r);
    cudaGetSymbolAddress((void**)&w2l, g_W2l);
    cudaGetSymbolAddress((void**)&w2r, g_W2r);
    cudaGetSymbolAddress((void**)&wo,  g_Wout);

    static cudaStream_t s_csr = nullptr;
    static cudaEvent_t ev_root = nullptr, ev_csr = nullptr;
    if (!s_csr) {
        cudaStreamCreateWithFlags(&s_csr, cudaStreamNonBlocking);
        cudaEventCreateWithFlags(&ev_root, cudaEventDisableTiming);
        cudaEventCreateWithFlags(&ev_csr, cudaEventDisableTiming);
    }

    // fork: CSR build on side stream
    cudaEventRecord(ev_root, 0);
    cudaStreamWaitEvent(s_csr, ev_root, 0);
    k_zero_detect<<<(Nn + 255) / 256, 256, 0, s_csr>>>((const int*)ei);
    k_hist<<<(ET / 4 + 255) / 256, 256, 0, s_csr>>>(ei);
    k_scan<<<1, 1024, 0, s_csr>>>();
    k_scatter<<<(ET / 4 + 255) / 256, 256, 0, s_csr>>>(ei);
    cudaEventRecord(ev_csr, s_csr);

    // main: weight prep then layer-1 GEMMs
    k_prep_weights<<<(4 * 65536 + DOUT * DH + 255) / 256, 256>>>(W1l, W1r, W2l, W2r, Wout);

    dim3 gDual(4, (Nn + 127) / 128);
    k_gemm_dual_f32<<<gDual, 256>>>(x, w1l, b1l, xl, w1r, b1r, xr, Nn, DH, DH);

    // join before GAT
    cudaStreamWaitEvent(0, ev_csr, 0);
    k_gat_layer<<<(Nn + 7) / 8, 256>>>(xl, xr, att1, bias1, h);

    // layer 2
    k_gemm_dual_f16<<<gDual, 256>>>(h, w2l, b2l, xl, w2r, b2r, xr, Nn, DH, DH);
    k_gat_layer<<<(Nn + 7) / 8, 256>>>(xl, xr, att2, bias2, h);

    // output head + log_softmax fused
    k_head_fused<<<(Nn + 127) / 128, 256>>>(h, wo, bout, out, Nn, DH);
}